// round 1
// baseline (speedup 1.0000x reference)
#include <cuda_runtime.h>
#include <math.h>

#define BB 64
#define TT 512
#define II 256
#define HH 1024

// ---------------- persistent recurrence state ----------------
#define RNN_BLOCKS 128
#define RNN_THREADS 256
#define COLS_PER_BLOCK 8
#define KSPLIT 4
#define KCHUNK (HH / KSPLIT)   // 256

// ping-pong hidden state, stored TRANSPOSED [H][B] for coalesced reads
__device__ float g_h[2][HH][BB];
__device__ unsigned g_bar_cnt = 0;
__device__ unsigned g_bar_gen = 0;

__device__ __forceinline__ void grid_barrier() {
    __syncthreads();
    if (threadIdx.x == 0) {
        unsigned gen = *((volatile unsigned*)&g_bar_gen);
        __threadfence();
        if (atomicAdd(&g_bar_cnt, 1u) == RNN_BLOCKS - 1) {
            g_bar_cnt = 0u;
            __threadfence();
            *((volatile unsigned*)&g_bar_gen) = gen + 1u;
        } else {
            while (*((volatile unsigned*)&g_bar_gen) == gen) { }
        }
        __threadfence();
    }
    __syncthreads();
}

// ---------------- input projection GEMM (fused bias + noise) ----------------
// out[m, n] = sum_i x[m,i] * in_w[n,i] + in_b[n] + 0.1f * eps[m,n]
// M = B*T = 32768, N = H = 1024, K = I = 256. Written into d_out (scratch reuse).
#define PBM 64
#define PBN 64
#define PBK 16

__global__ void __launch_bounds__(256)
proj_kernel(const float* __restrict__ x, const float* __restrict__ eps,
            const float* __restrict__ in_w, const float* __restrict__ in_b,
            float* __restrict__ out) {
    __shared__ float As[PBK][68];   // padded: conflict-light transposed stores, 16B-aligned rows
    __shared__ float Bs[PBK][68];

    const int tid = threadIdx.x;
    const int tx = tid & 15;        // 16 col-groups
    const int ty = tid >> 4;        // 16 row-groups
    const int m0 = blockIdx.y * PBM;
    const int n0 = blockIdx.x * PBN;
    const int lr = tid >> 2;        // load row 0..63
    const int lk = (tid & 3) << 2;  // load k offset {0,4,8,12}

    float acc[4][4];
    #pragma unroll
    for (int i = 0; i < 4; i++)
        #pragma unroll
        for (int j = 0; j < 4; j++) acc[i][j] = 0.0f;

    for (int k0 = 0; k0 < II; k0 += PBK) {
        float4 av = *(const float4*)&x[(size_t)(m0 + lr) * II + k0 + lk];
        float4 bv = *(const float4*)&in_w[(size_t)(n0 + lr) * II + k0 + lk];
        __syncthreads();
        As[lk + 0][lr] = av.x; As[lk + 1][lr] = av.y;
        As[lk + 2][lr] = av.z; As[lk + 3][lr] = av.w;
        Bs[lk + 0][lr] = bv.x; Bs[lk + 1][lr] = bv.y;
        Bs[lk + 2][lr] = bv.z; Bs[lk + 3][lr] = bv.w;
        __syncthreads();
        #pragma unroll
        for (int kk = 0; kk < PBK; kk++) {
            float4 a4 = *(const float4*)&As[kk][ty << 2];
            float4 b4 = *(const float4*)&Bs[kk][tx << 2];
            float a[4] = {a4.x, a4.y, a4.z, a4.w};
            float b[4] = {b4.x, b4.y, b4.z, b4.w};
            #pragma unroll
            for (int i = 0; i < 4; i++)
                #pragma unroll
                for (int j = 0; j < 4; j++)
                    acc[i][j] += a[i] * b[j];
        }
    }

    const float4 bias = *(const float4*)&in_b[n0 + (tx << 2)];
    #pragma unroll
    for (int i = 0; i < 4; i++) {
        size_t idx = (size_t)(m0 + (ty << 2) + i) * HH + n0 + (tx << 2);
        float4 ev = *(const float4*)&eps[idx];
        float4 o;
        o.x = acc[i][0] + bias.x + 0.1f * ev.x;
        o.y = acc[i][1] + bias.y + 0.1f * ev.y;
        o.z = acc[i][2] + bias.z + 0.1f * ev.z;
        o.w = acc[i][3] + bias.w + 0.1f * ev.w;
        *(float4*)&out[idx] = o;
    }
}

// ---------------- persistent recurrence kernel ----------------
// Each of 128 blocks owns 8 output columns. W[:, c0..c0+8) cached in SMEM once.
// Per step: 4-way K-split partial GEMM -> SMEM reduce -> leaky/tanh update
// -> write h slice (t) to out and new h to ping-pong buffer -> grid barrier.
__global__ void __launch_bounds__(RNN_THREADS, 1)
rnn_kernel(const float* __restrict__ W, const float* __restrict__ taus,
           float* __restrict__ out) {
    __shared__ float Ws[HH][COLS_PER_BLOCK];                   // 32 KB
    __shared__ float part[KSPLIT][BB][COLS_PER_BLOCK + 1];     // 9 KB, padded

    const int tid = threadIdx.x;
    const int c0 = blockIdx.x * COLS_PER_BLOCK;

    // load W column slice once (reused for all 512 steps)
    for (int i = tid; i < HH * COLS_PER_BLOCK; i += RNN_THREADS) {
        int k = i >> 3, c = i & 7;
        Ws[k][c] = W[(size_t)k * HH + c0 + c];
    }

    const int row = tid & 63;       // batch index
    const int grp = tid >> 6;       // 0..3, K-split group; also owns 2 output cols
    const int cc0 = grp * 2;
    const int cc1 = grp * 2 + 1;

    float alpha0, alpha1;
    {
        float t0 = taus[c0 + cc0];
        float t1 = taus[c0 + cc1];
        float s0 = 1.0f / (1.0f + expf(-t0));
        float s1 = 1.0f / (1.0f + expf(-t1));
        alpha0 = 10.0f / (s0 * 90.0f + 10.0f);
        alpha1 = 10.0f / (s1 * 90.0f + 10.0f);
    }

    // zero-init read buffer (h0 = 0); deterministic every launch
    g_h[0][c0 + cc0][row] = 0.0f;
    g_h[0][c0 + cc1][row] = 0.0f;
    float h0 = 0.0f, h1 = 0.0f;     // register copy of own h entries

    grid_barrier();

    for (int t = 0; t < TT; t++) {
        const int p = t & 1;
        const float* hb = &g_h[p][grp * KCHUNK][0];   // [k][row], k in this group's chunk
        float acc[8];
        #pragma unroll
        for (int j = 0; j < 8; j++) acc[j] = 0.0f;

        #pragma unroll 8
        for (int kk = 0; kk < KCHUNK; kk++) {
            float hv = __ldcg(hb + (size_t)kk * BB + row);     // L2 (cross-SM coherent)
            const float4 wa = *(const float4*)&Ws[grp * KCHUNK + kk][0];
            const float4 wb = *(const float4*)&Ws[grp * KCHUNK + kk][4];
            acc[0] += hv * wa.x;  acc[1] += hv * wa.y;
            acc[2] += hv * wa.z;  acc[3] += hv * wa.w;
            acc[4] += hv * wb.x;  acc[5] += hv * wb.y;
            acc[6] += hv * wb.z;  acc[7] += hv * wb.w;
        }

        #pragma unroll
        for (int j = 0; j < 8; j++) part[grp][row][j] = acc[j];
        __syncthreads();

        float s0 = part[0][row][cc0] + part[1][row][cc0]
                 + part[2][row][cc0] + part[3][row][cc0];
        float s1 = part[0][row][cc1] + part[1][row][cc1]
                 + part[2][row][cc1] + part[3][row][cc1];

        float* po = out + ((size_t)row * TT + t) * HH + c0;
        float pt0 = po[cc0];                 // proj + bias + noise (fused by proj_kernel)
        float pt1 = po[cc1];
        float hn0 = (1.0f - alpha0) * h0 + alpha0 * tanhf(pt0 + s0);
        float hn1 = (1.0f - alpha1) * h1 + alpha1 * tanhf(pt1 + s1);
        po[cc0] = hn0;                       // output slice for time t
        po[cc1] = hn1;

        const int np = p ^ 1;
        __stcg(&g_h[np][c0 + cc0][row], hn0);  // straight to L2
        __stcg(&g_h[np][c0 + cc1][row], hn1);
        h0 = hn0; h1 = hn1;

        grid_barrier();
    }
}

// ---------------- launcher ----------------
extern "C" void kernel_launch(void* const* d_in, const int* in_sizes, int n_in,
                              void* d_out, int out_size) {
    const float* x    = (const float*)d_in[0];
    const float* eps  = (const float*)d_in[1];
    const float* in_w = (const float*)d_in[2];
    const float* in_b = (const float*)d_in[3];
    const float* W    = (const float*)d_in[4];
    const float* taus = (const float*)d_in[5];
    float* out = (float*)d_out;

    dim3 pgrid(HH / PBN, (BB * TT) / PBM);
    proj_kernel<<<pgrid, 256>>>(x, eps, in_w, in_b, out);
    rnn_kernel<<<RNN_BLOCKS, RNN_THREADS>>>(W, taus, out);
}

// round 7
// speedup vs baseline: 1.5553x; 1.5553x over previous
#include <cuda_runtime.h>
#include <math.h>

#define BB 64
#define TT 512
#define II 256
#define HH 1024

// ---------------- persistent recurrence config ----------------
// 128 blocks = 64 column-groups (16 cols each) x 2 row-halves (32 rows each).
#define RNN_BLOCKS 128
#define RNN_THREADS 1024
#define COLS 16            // output columns per block
#define ROWS 32            // batch rows per block
#define KSPLIT 32
#define KCHUNK (HH / KSPLIT)   // 32

// ping-pong hidden state, stored TRANSPOSED [H][B] for coalesced reads
__device__ float g_h[2][HH][BB];
__device__ unsigned g_bar_cnt = 0;
__device__ unsigned g_bar_gen = 0;

__device__ __forceinline__ void grid_barrier() {
    __syncthreads();
    if (threadIdx.x == 0) {
        unsigned gen = *((volatile unsigned*)&g_bar_gen);
        __threadfence();
        if (atomicAdd(&g_bar_cnt, 1u) == RNN_BLOCKS - 1) {
            g_bar_cnt = 0u;
            __threadfence();
            *((volatile unsigned*)&g_bar_gen) = gen + 1u;
        } else {
            while (*((volatile unsigned*)&g_bar_gen) == gen) { }
        }
        __threadfence();
    }
    __syncthreads();
}

__device__ __forceinline__ float fast_tanh(float z) {
    z = fminf(fmaxf(z, -20.0f), 20.0f);
    float e = __expf(2.0f * z);
    return (e - 1.0f) / (e + 1.0f);
}

// packed f32x2 helpers (Blackwell packed fp32 pipe; 2 FMAs per instruction)
__device__ __forceinline__ unsigned long long pack2(float x) {
    unsigned long long r;
    asm("mov.b64 %0, {%1, %1};" : "=l"(r) : "f"(x));
    return r;
}
__device__ __forceinline__ void fma2(unsigned long long& d,
                                     unsigned long long a,
                                     unsigned long long b) {
    asm("fma.rn.f32x2 %0, %1, %2, %0;" : "+l"(d) : "l"(a), "l"(b));
}

// ---------------- input projection GEMM (fused bias + noise) ----------------
// out[m, n] = sum_i x[m,i]*in_w[n,i] + in_b[n] + 0.1f*eps[m,n]
#define PBM 64
#define PBN 64
#define PBK 16

__global__ void __launch_bounds__(256)
proj_kernel(const float* __restrict__ x, const float* __restrict__ eps,
            const float* __restrict__ in_w, const float* __restrict__ in_b,
            float* __restrict__ out) {
    __shared__ float As[PBK][68];
    __shared__ float Bs[PBK][68];

    const int tid = threadIdx.x;
    const int tx = tid & 15;
    const int ty = tid >> 4;
    const int m0 = blockIdx.y * PBM;
    const int n0 = blockIdx.x * PBN;
    const int lr = tid >> 2;
    const int lk = (tid & 3) << 2;

    float acc[4][4];
    #pragma unroll
    for (int i = 0; i < 4; i++)
        #pragma unroll
        for (int j = 0; j < 4; j++) acc[i][j] = 0.0f;

    for (int k0 = 0; k0 < II; k0 += PBK) {
        float4 av = *(const float4*)&x[(size_t)(m0 + lr) * II + k0 + lk];
        float4 bv = *(const float4*)&in_w[(size_t)(n0 + lr) * II + k0 + lk];
        __syncthreads();
        As[lk + 0][lr] = av.x; As[lk + 1][lr] = av.y;
        As[lk + 2][lr] = av.z; As[lk + 3][lr] = av.w;
        Bs[lk + 0][lr] = bv.x; Bs[lk + 1][lr] = bv.y;
        Bs[lk + 2][lr] = bv.z; Bs[lk + 3][lr] = bv.w;
        __syncthreads();
        #pragma unroll
        for (int kk = 0; kk < PBK; kk++) {
            float4 a4 = *(const float4*)&As[kk][ty << 2];
            float4 b4 = *(const float4*)&Bs[kk][tx << 2];
            float a[4] = {a4.x, a4.y, a4.z, a4.w};
            float b[4] = {b4.x, b4.y, b4.z, b4.w};
            #pragma unroll
            for (int i = 0; i < 4; i++)
                #pragma unroll
                for (int j = 0; j < 4; j++)
                    acc[i][j] += a[i] * b[j];
        }
    }

    const float4 bias = *(const float4*)&in_b[n0 + (tx << 2)];
    #pragma unroll
    for (int i = 0; i < 4; i++) {
        size_t idx = (size_t)(m0 + (ty << 2) + i) * HH + n0 + (tx << 2);
        float4 ev = *(const float4*)&eps[idx];
        float4 o;
        o.x = acc[i][0] + bias.x + 0.1f * ev.x;
        o.y = acc[i][1] + bias.y + 0.1f * ev.y;
        o.z = acc[i][2] + bias.z + 0.1f * ev.z;
        o.w = acc[i][3] + bias.w + 0.1f * ev.w;
        *(float4*)&out[idx] = o;
    }
}

// ---------------- persistent recurrence kernel ----------------
// Dynamic SMEM layout:
//   Ws   [HH][COLS]            16384 floats (64 KB)  - W column slice, loaded once
//   part [KSPLIT][ROWS][17]    17408 floats (68 KB)  - per-group partials (pad 17)
//   red  [ROWS][17]              544 floats (2.1 KB) - upper-half reduction buffer
__global__ void __launch_bounds__(RNN_THREADS, 1)
rnn_kernel(const float* __restrict__ W, const float* __restrict__ taus,
           float* __restrict__ out) {
    extern __shared__ float smem[];
    float* Ws   = smem;                  // [k*16 + c]
    float* part = smem + HH * COLS;      // [(g*32+row)*17 + c]
    float* red  = part + KSPLIT * ROWS * 17;

    const int tid = threadIdx.x;
    const int cg = blockIdx.x >> 1;
    const int c0 = cg * COLS;
    const int r0 = (blockIdx.x & 1) * ROWS;

    // load W column slice once (coalesced over W row-major)
    for (int i = tid; i < HH * COLS; i += RNN_THREADS) {
        int k = i >> 4, c = i & 15;
        Ws[i] = W[(size_t)k * HH + c0 + c];
    }

    // GEMM-phase mapping: lane = local row (coalesced h reads), warp = one grp
    const int row = tid & 31;       // 0..31 local batch row
    const int grp = tid >> 5;       // 0..31 K-split group

    // epilogue mapping: 512 outputs, two reduction halves
    const int o    = tid & 511;
    const int lrow = o >> 4;        // 0..31
    const int col  = o & 15;        // 0..15
    const int half = tid >> 9;      // 0: final update, 1: upper-half reduce

    float alpha = 0.0f, one_m_alpha = 0.0f, hreg = 0.0f, pt_next = 0.0f;
    if (half == 0) {
        float tv = taus[c0 + col];
        float s = 1.0f / (1.0f + __expf(-tv));
        alpha = 10.0f / (s * 90.0f + 10.0f);
        one_m_alpha = 1.0f - alpha;
        g_h[0][c0 + col][r0 + lrow] = 0.0f;   // h0 = 0, deterministic
        pt_next = out[((size_t)(r0 + lrow) * TT + 0) * HH + c0 + col];
    }

    grid_barrier();

    for (int t = 0; t < TT; t++) {
        const int p = t & 1;
        const float* hp = &g_h[p][grp * KCHUNK][0] + r0 + row;   // stride BB per k

        unsigned long long acc[8];
        #pragma unroll
        for (int i = 0; i < 8; i++) acc[i] = 0ull;

        // software-pipelined: 4 groups of 8 k-values
        float hv[8];
        #pragma unroll
        for (int j = 0; j < 8; j++) hv[j] = __ldcg(hp + j * BB);

        #pragma unroll
        for (int kb = 0; kb < KCHUNK / 8; kb++) {
            float hn8[8];
            if (kb < KCHUNK / 8 - 1) {
                #pragma unroll
                for (int j = 0; j < 8; j++)
                    hn8[j] = __ldcg(hp + (kb * 8 + 8 + j) * BB);
            }
            #pragma unroll
            for (int j = 0; j < 8; j++) {
                const int k = kb * 8 + j;
                const unsigned long long* wr =
                    (const unsigned long long*)(Ws + (grp * KCHUNK + k) * COLS);
                const unsigned long long hh = pack2(hv[j]);
                fma2(acc[0], wr[0], hh); fma2(acc[1], wr[1], hh);
                fma2(acc[2], wr[2], hh); fma2(acc[3], wr[3], hh);
                fma2(acc[4], wr[4], hh); fma2(acc[5], wr[5], hh);
                fma2(acc[6], wr[6], hh); fma2(acc[7], wr[7], hh);
            }
            if (kb < KCHUNK / 8 - 1) {
                #pragma unroll
                for (int j = 0; j < 8; j++) hv[j] = hn8[j];
            }
        }

        // store partials (bank-conflict-free: row stride 17, rows distinct in warp)
        {
            float* pb = part + (grp * ROWS + row) * 17;
            #pragma unroll
            for (int i = 0; i < 8; i++) {
                union { unsigned long long u; float2 f; } cv; cv.u = acc[i];
                pb[2 * i]     = cv.f.x;
                pb[2 * i + 1] = cv.f.y;
            }
        }
        __syncthreads();

        // split reduce: half1 sums groups 16..31 into red, half0 sums 0..15
        float s = 0.0f;
        if (half == 1) {
            #pragma unroll
            for (int g = 16; g < 32; g++) s += part[(g * ROWS + lrow) * 17 + col];
            red[lrow * 17 + col] = s;
        } else {
            #pragma unroll
            for (int g = 0; g < 16; g++) s += part[(g * ROWS + lrow) * 17 + col];
        }
        __syncthreads();

        if (half == 0) {
            s += red[lrow * 17 + col];
            float hn = one_m_alpha * hreg + alpha * fast_tanh(pt_next + s);

            float* po = out + ((size_t)(r0 + lrow) * TT + t) * HH + c0 + col;
            if (t + 1 < TT) pt_next = po[HH];   // prefetch pt for t+1
            *po = hn;                           // output slice for time t

            __stcg(&g_h[p ^ 1][c0 + col][r0 + lrow], hn);
            hreg = hn;
        }

        grid_barrier();
    }
}

// ---------------- launcher ----------------
extern "C" void kernel_launch(void* const* d_in, const int* in_sizes, int n_in,
                              void* d_out, int out_size) {
    const float* x    = (const float*)d_in[0];
    const float* eps  = (const float*)d_in[1];
    const float* in_w = (const float*)d_in[2];
    const float* in_b = (const float*)d_in[3];
    const float* W    = (const float*)d_in[4];
    const float* taus = (const float*)d_in[5];
    float* out = (float*)d_out;

    const int rnn_smem = (HH * COLS + KSPLIT * ROWS * 17 + ROWS * 17) * 4;
    static int attr_set = 0;
    if (!attr_set) {
        cudaFuncSetAttribute(rnn_kernel,
                             cudaFuncAttributeMaxDynamicSharedMemorySize,
                             rnn_smem);
        attr_set = 1;
    }

    dim3 pgrid(HH / PBN, (BB * TT) / PBM);
    proj_kernel<<<pgrid, 256>>>(x, eps, in_w, in_b, out);
    rnn_kernel<<<RNN_BLOCKS, RNN_THREADS, rnn_smem>>>(W, taus, out);
}

// round 10
// speedup vs baseline: 1.9925x; 1.2811x over previous
#include <cuda_runtime.h>
#include <math.h>

#define BB 64
#define TT 512
#define II 256
#define HH 1024

// ---------------- persistent recurrence config ----------------
// 128 blocks = 128 column-groups (8 cols each), all 64 batch rows per block.
#define RNN_BLOCKS 128
#define RNN_THREADS 1024
#define COLS 8
#define KSPLIT 32
#define KCHUNK (HH / KSPLIT)   // 32

// part layout: [g][c][r(64)+4 pad]  -> per-g stride 8*68 = 544 floats
#define CSTRIDE 68
#define GSTRIDE (COLS * CSTRIDE)   // 544

// ping-pong hidden state, stored TRANSPOSED [H][B] for coalesced reads
__device__ float g_h[2][HH][BB];
__device__ unsigned g_bar_cnt = 0;
__device__ unsigned g_bar_gen = 0;

__device__ __forceinline__ void grid_barrier() {
    __syncthreads();
    if (threadIdx.x == 0) {
        unsigned gen = *((volatile unsigned*)&g_bar_gen);
        __threadfence();
        if (atomicAdd(&g_bar_cnt, 1u) == RNN_BLOCKS - 1) {
            g_bar_cnt = 0u;
            __threadfence();
            *((volatile unsigned*)&g_bar_gen) = gen + 1u;
        } else {
            while (*((volatile unsigned*)&g_bar_gen) == gen) { }
        }
        __threadfence();
    }
    __syncthreads();
}

__device__ __forceinline__ float fast_tanh(float z) {
    z = fminf(fmaxf(z, -20.0f), 20.0f);
    float e = __expf(2.0f * z);
    return (e - 1.0f) / (e + 1.0f);
}

// packed f32x2 helpers
__device__ __forceinline__ unsigned long long pack2(float x) {
    unsigned long long r;
    asm("mov.b64 %0, {%1, %1};" : "=l"(r) : "f"(x));
    return r;
}
__device__ __forceinline__ void fma2(unsigned long long& d,
                                     unsigned long long a,
                                     unsigned long long b) {
    asm("fma.rn.f32x2 %0, %1, %2, %0;" : "+l"(d) : "l"(a), "l"(b));
}
__device__ __forceinline__ void unpack2(unsigned long long v, float& lo, float& hi) {
    asm("mov.b64 {%0, %1}, %2;" : "=f"(lo), "=f"(hi) : "l"(v));
}

// ---------------- input projection GEMM (fused bias + noise) ----------------
#define PBM 64
#define PBN 64
#define PBK 16

__global__ void __launch_bounds__(256)
proj_kernel(const float* __restrict__ x, const float* __restrict__ eps,
            const float* __restrict__ in_w, const float* __restrict__ in_b,
            float* __restrict__ out) {
    __shared__ float As[PBK][68];
    __shared__ float Bs[PBK][68];

    const int tid = threadIdx.x;
    const int tx = tid & 15;
    const int ty = tid >> 4;
    const int m0 = blockIdx.y * PBM;
    const int n0 = blockIdx.x * PBN;
    const int lr = tid >> 2;
    const int lk = (tid & 3) << 2;

    float acc[4][4];
    #pragma unroll
    for (int i = 0; i < 4; i++)
        #pragma unroll
        for (int j = 0; j < 4; j++) acc[i][j] = 0.0f;

    for (int k0 = 0; k0 < II; k0 += PBK) {
        float4 av = *(const float4*)&x[(size_t)(m0 + lr) * II + k0 + lk];
        float4 bv = *(const float4*)&in_w[(size_t)(n0 + lr) * II + k0 + lk];
        __syncthreads();
        As[lk + 0][lr] = av.x; As[lk + 1][lr] = av.y;
        As[lk + 2][lr] = av.z; As[lk + 3][lr] = av.w;
        Bs[lk + 0][lr] = bv.x; Bs[lk + 1][lr] = bv.y;
        Bs[lk + 2][lr] = bv.z; Bs[lk + 3][lr] = bv.w;
        __syncthreads();
        #pragma unroll
        for (int kk = 0; kk < PBK; kk++) {
            float4 a4 = *(const float4*)&As[kk][ty << 2];
            float4 b4 = *(const float4*)&Bs[kk][tx << 2];
            float a[4] = {a4.x, a4.y, a4.z, a4.w};
            float b[4] = {b4.x, b4.y, b4.z, b4.w};
            #pragma unroll
            for (int i = 0; i < 4; i++)
                #pragma unroll
                for (int j = 0; j < 4; j++)
                    acc[i][j] += a[i] * b[j];
        }
    }

    const float4 bias = *(const float4*)&in_b[n0 + (tx << 2)];
    #pragma unroll
    for (int i = 0; i < 4; i++) {
        size_t idx = (size_t)(m0 + (ty << 2) + i) * HH + n0 + (tx << 2);
        float4 ev = *(const float4*)&eps[idx];
        float4 o;
        o.x = acc[i][0] + bias.x + 0.1f * ev.x;
        o.y = acc[i][1] + bias.y + 0.1f * ev.y;
        o.z = acc[i][2] + bias.z + 0.1f * ev.z;
        o.w = acc[i][3] + bias.w + 0.1f * ev.w;
        *(float4*)&out[idx] = o;
    }
}

// ---------------- persistent recurrence kernel ----------------
// Dynamic SMEM:
//   Ws   [HH][COLS]          8192 floats (32 KB)   - W column slice (8 cols)
//   part [KSPLIT][COLS][68] 17408 floats (68 KB)   - partials, [g][c][r+pad]
//   red  [512]                512 floats (2 KB)    - upper-half reduction
__global__ void __launch_bounds__(RNN_THREADS, 1)
rnn_kernel(const float* __restrict__ W, const float* __restrict__ taus,
           float* __restrict__ out) {
    extern __shared__ float smem[];
    float* Ws   = smem;                    // [k*8 + c]
    float* part = smem + HH * COLS;        // [g*544 + c*68 + r]
    float* red  = part + KSPLIT * GSTRIDE;

    const int tid = threadIdx.x;
    const int c0 = blockIdx.x * COLS;

    // load W column slice once
    for (int i = tid; i < HH * COLS; i += RNN_THREADS) {
        int k = i >> 3, c = i & 7;
        Ws[i] = W[(size_t)k * HH + c0 + c];
    }

    // GEMM mapping: warp = k-group, lane = row-pair (rows 2L, 2L+1)
    const int lane = tid & 31;
    const int grp  = tid >> 5;      // 0..31

    // epilogue mapping (tid < 512): o = r*8 + c
    const int o   = tid & 511;
    const int ecol = o & 7;
    const int erow = o >> 3;        // 0..63
    const int half = tid >> 9;      // 0: update, 1: upper-half reduce

    float alpha = 0.0f, one_m_alpha = 0.0f, hreg = 0.0f, pt_next = 0.0f;
    if (half == 0) {
        float tv = taus[c0 + ecol];
        float s = 1.0f / (1.0f + __expf(-tv));
        alpha = 10.0f / (s * 90.0f + 10.0f);
        one_m_alpha = 1.0f - alpha;
        g_h[0][c0 + ecol][erow] = 0.0f;    // h0 = 0, deterministic
        pt_next = out[((size_t)erow * TT + 0) * HH + c0 + ecol];
    }

    grid_barrier();

    for (int t = 0; t < TT; t++) {
        const int p = t & 1;
        // h float2 pointer: element k -> g_h[p][grp*KCHUNK + k][2*lane]
        const float2* hp = (const float2*)(&g_h[p][grp * KCHUNK][0]) + lane;

        unsigned long long accA[4], accB[4];   // rows 2L / 2L+1, col-pairs 0..3
        #pragma unroll
        for (int i = 0; i < 4; i++) { accA[i] = 0ull; accB[i] = 0ull; }

        // software pipeline: groups of 4 k
        float2 hv[4];
        #pragma unroll
        for (int j = 0; j < 4; j++)
            hv[j] = __ldcg(hp + (size_t)j * (BB / 2));

        #pragma unroll
        for (int kb = 0; kb < KCHUNK / 4; kb++) {
            float2 hn4[4];
            if (kb < KCHUNK / 4 - 1) {
                #pragma unroll
                for (int j = 0; j < 4; j++)
                    hn4[j] = __ldcg(hp + (size_t)(kb * 4 + 4 + j) * (BB / 2));
            }
            #pragma unroll
            for (int j = 0; j < 4; j++) {
                const int k = kb * 4 + j;
                const float* wr = Ws + (grp * KCHUNK + k) * COLS;
                const ulonglong2 wA = *(const ulonglong2*)wr;       // c0c1, c2c3
                const ulonglong2 wB = *(const ulonglong2*)(wr + 4); // c4c5, c6c7
                const unsigned long long hx = pack2(hv[j].x);
                const unsigned long long hy = pack2(hv[j].y);
                fma2(accA[0], wA.x, hx); fma2(accA[1], wA.y, hx);
                fma2(accA[2], wB.x, hx); fma2(accA[3], wB.y, hx);
                fma2(accB[0], wA.x, hy); fma2(accB[1], wA.y, hy);
                fma2(accB[2], wB.x, hy); fma2(accB[3], wB.y, hy);
            }
            if (kb < KCHUNK / 4 - 1) {
                #pragma unroll
                for (int j = 0; j < 4; j++) hv[j] = hn4[j];
            }
        }

        // store partials: part[g][c][r], r = 2*lane (+1). STS.64 per col, degree-2.
        {
            float* pb = part + grp * GSTRIDE + 2 * lane;
            #pragma unroll
            for (int cp = 0; cp < 4; cp++) {
                float a_lo, a_hi, b_lo, b_hi;
                unpack2(accA[cp], a_lo, a_hi);   // row 2L: cols 2cp, 2cp+1
                unpack2(accB[cp], b_lo, b_hi);   // row 2L+1
                float2 v0 = make_float2(a_lo, b_lo);   // col 2cp, rows 2L..2L+1
                float2 v1 = make_float2(a_hi, b_hi);   // col 2cp+1
                *(float2*)(pb + (2 * cp) * CSTRIDE)     = v0;
                *(float2*)(pb + (2 * cp + 1) * CSTRIDE) = v1;
            }
        }
        __syncthreads();

        // split reduce: half1 sums g=16..31 into red, half0 sums g=0..15
        {
            const float* pr = part + ecol * CSTRIDE + erow;
            float s = 0.0f;
            if (half == 1) {
                #pragma unroll
                for (int g = 16; g < 32; g++) s += pr[g * GSTRIDE];
                red[o] = s;
            } else {
                #pragma unroll
                for (int g = 0; g < 16; g++) s += pr[g * GSTRIDE];

                __syncthreads();
                s += red[o];

                float hn = one_m_alpha * hreg + alpha * fast_tanh(pt_next + s);

                float* po = out + ((size_t)erow * TT + t) * HH + c0 + ecol;
                if (t + 1 < TT) pt_next = po[HH];   // prefetch pt for t+1
                *po = hn;                           // output slice for time t

                __stcg(&g_h[p ^ 1][c0 + ecol][erow], hn);
                hreg = hn;
            }
            if (half == 1) __syncthreads();         // match half0's second sync
        }

        grid_barrier();
    }
}

// ---------------- launcher ----------------
extern "C" void kernel_launch(void* const* d_in, const int* in_sizes, int n_in,
                              void* d_out, int out_size) {
    const float* x    = (const float*)d_in[0];
    const float* eps  = (const float*)d_in[1];
    const float* in_w = (const float*)d_in[2];
    const float* in_b = (const float*)d_in[3];
    const float* W    = (const float*)d_in[4];
    const float* taus = (const float*)d_in[5];
    float* out = (float*)d_out;

    const int rnn_smem = (HH * COLS + KSPLIT * GSTRIDE + 512) * 4;
    static int attr_set = 0;
    if (!attr_set) {
        cudaFuncSetAttribute(rnn_kernel,
                             cudaFuncAttributeMaxDynamicSharedMemorySize,
                             rnn_smem);
        attr_set = 1;
    }

    dim3 pgrid(HH / PBN, (BB * TT) / PBM);
    proj_kernel<<<pgrid, 256>>>(x, eps, in_w, in_b, out);
    rnn_kernel<<<RNN_BLOCKS, RNN_THREADS, rnn_smem>>>(W, taus, out);
}